// round 4
// baseline (speedup 1.0000x reference)
#include <cuda_runtime.h>

// SpanRepLayer: start / inner-maxpool / end span representations.
// B=2, NS=512, S=1024, H=128, MAX_W=16. Output (B, NS, 3H) fp32.
//
// Inputs (metadata order):
//   d_in[0]: token_reps (B, S, H)  float32
//   d_in[1]: span_ids   (B, NS, 2) int32   [start, end+1]
//   d_in[2]: span_masks (B, NS)    int32 (bool promoted)
// Output: (B, NS, 3H) float32
//
// Shape notes: 1 warp per span, 8 warps/CTA -> grid=128 (single wave on 148 SMs).
// No divergent masked path: compute unconditionally, scale by mask at the end
// (span_ids are valid even for masked spans; reference zeroes masked rows).

#define SRL_NS 512
#define SRL_S  1024
#define SRL_NSPANS (2 * SRL_NS)
#define MAX_INNER 14         // MAX_W=16 -> inner length <= 14
 
__global__ __launch_bounds__(256) void span_rep_kernel(
    const float* __restrict__ token_reps,
    const int2* __restrict__ span_ids,
    const int* __restrict__ span_masks,
    float* __restrict__ out)
{
    const int span = blockIdx.x * 8 + (threadIdx.x >> 5);  // 8 warps/block, 1 span/warp
    const int lane = threadIdx.x & 31;

    // Issue mask and ids loads back-to-back (independent -> overlapped latency).
    const int   mask_i = span_masks[span];
    const int2  ids    = span_ids[span];
    const float m      = mask_i ? 1.0f : 0.0f;

    const int start = ids.x;
    const int end   = ids.y - 1;            // inclusive
    const int inner_len = end - start - 1;  // may be <= 0

    const int b = span >> 9;                // span / SRL_NS
    const float4* __restrict__ base =
        reinterpret_cast<const float4*>(token_reps) + (size_t)b * SRL_S * 32 + lane;

    // All row loads issued in one batch: start, end, 14 clamped inner rows.
    const float4 sr = base[start * 32];
    const float4 er = base[end * 32];

    const int last_i = (inner_len > 0 ? inner_len : 1) - 1;
    float4 v[MAX_INNER];
    #pragma unroll
    for (int i = 0; i < MAX_INNER; ++i) {
        int ii = i < last_i ? i : last_i;
        v[i] = base[(start + 1 + ii) * 32];
    }

    float4 inner;
    if (inner_len > 0) {
        inner = v[0];
        #pragma unroll
        for (int i = 1; i < MAX_INNER; ++i) {
            if (i < inner_len) {
                inner.x = fmaxf(inner.x, v[i].x);
                inner.y = fmaxf(inner.y, v[i].y);
                inner.z = fmaxf(inner.z, v[i].z);
                inner.w = fmaxf(inner.w, v[i].w);
            }
        }
    } else {
        inner = sr;   // no inner tokens -> start rep
    }

    float4* o = reinterpret_cast<float4*>(out) + (size_t)span * 96;  // 3H = 96 float4
    o[lane]      = make_float4(sr.x * m,    sr.y * m,    sr.z * m,    sr.w * m);
    o[lane + 32] = make_float4(inner.x * m, inner.y * m, inner.z * m, inner.w * m);
    o[lane + 64] = make_float4(er.x * m,    er.y * m,    er.z * m,    er.w * m);
}

extern "C" void kernel_launch(void* const* d_in, const int* in_sizes, int n_in,
                              void* d_out, int out_size)
{
    const float* token_reps = (const float*)d_in[0];
    const int2* span_ids    = (const int2*)d_in[1];
    const int* span_masks   = (const int*)d_in[2];
    float* out              = (float*)d_out;

    span_rep_kernel<<<SRL_NSPANS / 8, 256>>>(token_reps, span_ids, span_masks, out);
}

// round 5
// speedup vs baseline: 1.0186x; 1.0186x over previous
#include <cuda_runtime.h>

// SpanRepLayer: start / inner-maxpool / end span representations.
// B=2, NS=512, S=1024, H=128, MAX_W=16. Output (B, NS, 3H) fp32.
//
// Inputs (metadata order):
//   d_in[0]: token_reps (B, S, H)  float32
//   d_in[1]: span_ids   (B, NS, 2) int32   [start, end+1]
//   d_in[2]: span_masks (B, NS)    int32 (bool promoted)
// Output: (B, NS, 3H) float32
//
// Parallelism: 2 warps per span (each lane owns a float2 of the H=128 row),
// 2048 warps total (~3.5 per SMSP) to hide memory latency. 8 warps/CTA,
// grid=256 -> still effectively latency-bound single pass.

#define SRL_NS 512
#define SRL_S  1024
#define SRL_NSPANS (2 * SRL_NS)
#define MAX_INNER 14         // MAX_W=16 -> inner length <= 14

__global__ __launch_bounds__(256) void span_rep_kernel(
    const float* __restrict__ token_reps,
    const int2* __restrict__ span_ids,
    const int* __restrict__ span_masks,
    float* __restrict__ out)
{
    const int gwarp = blockIdx.x * 8 + (threadIdx.x >> 5);  // 0..2047
    const int span  = gwarp >> 1;                           // 2 warps per span
    const int half  = gwarp & 1;
    const int lane  = threadIdx.x & 31;
    const int slot  = half * 32 + lane;                     // 0..63 float2 slots per row

    // Independent scalar loads issued together.
    const int  mask_i = span_masks[span];
    const int2 ids    = span_ids[span];
    const float m     = mask_i ? 1.0f : 0.0f;

    const int start = ids.x;
    const int end   = ids.y - 1;            // inclusive
    const int inner_len = end - start - 1;  // may be <= 0

    const int b = span >> 9;                // span / SRL_NS
    const float2* __restrict__ base =
        reinterpret_cast<const float2*>(token_reps) + (size_t)b * SRL_S * 64 + slot;

    // One batch of loads: start, end, 14 clamped inner rows.
    const float2 sr = base[start * 64];
    const float2 er = base[end * 64];

    const int last_i = (inner_len > 0 ? inner_len : 1) - 1;
    float2 v[MAX_INNER];
    #pragma unroll
    for (int i = 0; i < MAX_INNER; ++i) {
        int ii = i < last_i ? i : last_i;
        v[i] = base[(start + 1 + ii) * 64];
    }

    float2 inner;
    if (inner_len > 0) {
        inner = v[0];
        #pragma unroll
        for (int i = 1; i < MAX_INNER; ++i) {
            if (i < inner_len) {
                inner.x = fmaxf(inner.x, v[i].x);
                inner.y = fmaxf(inner.y, v[i].y);
            }
        }
    } else {
        inner = sr;   // no inner tokens -> start rep
    }

    float2* o = reinterpret_cast<float2*>(out) + (size_t)span * 192;  // 3H = 192 float2
    o[slot]       = make_float2(sr.x * m,    sr.y * m);
    o[slot + 64]  = make_float2(inner.x * m, inner.y * m);
    o[slot + 128] = make_float2(er.x * m,    er.y * m);
}

extern "C" void kernel_launch(void* const* d_in, const int* in_sizes, int n_in,
                              void* d_out, int out_size)
{
    const float* token_reps = (const float*)d_in[0];
    const int2* span_ids    = (const int2*)d_in[1];
    const int* span_masks   = (const int*)d_in[2];
    float* out              = (float*)d_out;

    // 2048 warps total, 8 warps (256 thr) per CTA -> 256 CTAs.
    span_rep_kernel<<<256, 256>>>(token_reps, span_ids, span_masks, out);
}

// round 6
// speedup vs baseline: 1.0234x; 1.0047x over previous
#include <cuda_runtime.h>

// SpanRepLayer: start / inner-maxpool / end span representations.
// B=2, NS=512, S=1024, H=128, MAX_W=16. Output (B, NS, 3H) fp32.
//
// Inputs (metadata order):
//   d_in[0]: token_reps (B, S, H)  float32
//   d_in[1]: span_ids   (B, NS, 2) int32   [start, end+1]
//   d_in[2]: span_masks (B, NS)    int32 (bool promoted)
// Output: (B, NS, 3H) float32
//
// Parallelism: 4 warps per span, one float channel per lane (4*32 = H=128).
// 4096 warps total (~7 per SMSP) — this kernel is concurrency-bound
// (confirmed R5: occ/issue scale with warp count and dur drops), so keep
// scaling warps while loads stay coalesced.

#define SRL_NS 512
#define SRL_S  1024
#define SRL_NSPANS (2 * SRL_NS)
#define MAX_INNER 14         // MAX_W=16 -> inner length <= 14

__global__ __launch_bounds__(512) void span_rep_kernel(
    const float* __restrict__ token_reps,
    const int2* __restrict__ span_ids,
    const int* __restrict__ span_masks,
    float* __restrict__ out)
{
    const int gwarp = blockIdx.x * 16 + (threadIdx.x >> 5);  // 0..4095
    const int span  = gwarp >> 2;                            // 4 warps per span
    const int quad  = gwarp & 3;
    const int lane  = threadIdx.x & 31;
    const int ch    = quad * 32 + lane;                      // 0..127 channel

    // Independent scalar loads issued together.
    const int  mask_i = span_masks[span];
    const int2 ids    = span_ids[span];
    const float m     = mask_i ? 1.0f : 0.0f;

    const int start = ids.x;
    const int end   = ids.y - 1;            // inclusive
    const int inner_len = end - start - 1;  // may be <= 0

    const int b = span >> 9;                // span / SRL_NS
    const float* __restrict__ base = token_reps + (size_t)b * SRL_S * 128 + ch;

    // One batch of loads: start, end, 14 clamped inner rows.
    const float sr = base[start * 128];
    const float er = base[end * 128];

    const int last_i = (inner_len > 0 ? inner_len : 1) - 1;
    float v[MAX_INNER];
    #pragma unroll
    for (int i = 0; i < MAX_INNER; ++i) {
        int ii = i < last_i ? i : last_i;
        v[i] = base[(start + 1 + ii) * 128];
    }

    float inner;
    if (inner_len > 0) {
        inner = v[0];
        #pragma unroll
        for (int i = 1; i < MAX_INNER; ++i) {
            if (i < inner_len) inner = fmaxf(inner, v[i]);
        }
    } else {
        inner = sr;   // no inner tokens -> start rep
    }

    float* o = out + (size_t)span * 384;   // 3H = 384 floats
    o[ch]       = sr * m;
    o[ch + 128] = inner * m;
    o[ch + 256] = er * m;
}

extern "C" void kernel_launch(void* const* d_in, const int* in_sizes, int n_in,
                              void* d_out, int out_size)
{
    const float* token_reps = (const float*)d_in[0];
    const int2* span_ids    = (const int2*)d_in[1];
    const int* span_masks   = (const int*)d_in[2];
    float* out              = (float*)d_out;

    // 4096 warps total, 16 warps (512 thr) per CTA -> 256 CTAs.
    span_rep_kernel<<<256, 512>>>(token_reps, span_ids, span_masks, out);
}

// round 7
// speedup vs baseline: 1.0529x; 1.0288x over previous
#include <cuda_runtime.h>

// SpanRepLayer: start / inner-maxpool / end span representations.
// B=2, NS=512, S=1024, H=128, MAX_W=16. Output (B, NS, 3H) fp32.
//
// Inputs (metadata order):
//   d_in[0]: token_reps (B, S, H)  float32
//   d_in[1]: span_ids   (B, NS, 2) int32   [start, end+1]
//   d_in[2]: span_masks (B, NS)    int32 (bool promoted)
// Output: (B, NS, 3H) float32
//
// Parallelism: 8 warps per span (8192 warps total, ~55/SM).
//   group0 (warps 0-3): start row + inner tokens 0..6  -> writes start & inner
//   group1 (warps 4-7): end row   + inner tokens 7..13 -> partial max via smem,
//                       writes end third.
// One span per 256-thread CTA, grid=1024 -> single wave at ~7 CTAs/SM.

#define SRL_NS 512
#define SRL_S  1024
#define SRL_NSPANS (2 * SRL_NS)

__global__ __launch_bounds__(256) void span_rep_kernel(
    const float* __restrict__ token_reps,
    const int2* __restrict__ span_ids,
    const int* __restrict__ span_masks,
    float* __restrict__ out)
{
    __shared__ float part1[128];

    const int span = blockIdx.x;
    const int wib  = threadIdx.x >> 5;     // 0..7
    const int g    = wib >> 2;             // group 0/1
    const int lane = threadIdx.x & 31;
    const int ch   = (wib & 3) * 32 + lane;  // 0..127 channel

    // Independent scalar loads issued together.
    const int  mask_i = span_masks[span];
    const int2 ids    = span_ids[span];
    const float m     = mask_i ? 1.0f : 0.0f;

    const int start = ids.x;
    const int end   = ids.y - 1;            // inclusive
    const int inner_len = end - start - 1;  // may be <= 0
    const int last_i = (inner_len > 0 ? inner_len : 1) - 1;

    const int b = span >> 9;
    const float* __restrict__ base = token_reps + (size_t)b * SRL_S * 128 + ch;

    // Edge row: start for group0, end for group1.
    const float edge = base[(g == 0 ? start : end) * 128];

    // 7 clamped inner-token loads per group (token index g*7 + i).
    float v[7];
    #pragma unroll
    for (int i = 0; i < 7; ++i) {
        int idx = g * 7 + i;
        int ii = idx < last_i ? idx : last_i;   // clamp -> always a valid address
        v[i] = base[(start + 1 + ii) * 128];
    }

    float p = -3.0e38f;
    #pragma unroll
    for (int i = 0; i < 7; ++i) {
        if (g * 7 + i < inner_len) p = fmaxf(p, v[i]);
    }

    if (g == 1) part1[ch] = p;
    __syncthreads();   // unconditional: all 256 threads reach this

    float* o = out + (size_t)span * 384;   // 3H = 384 floats
    if (g == 0) {
        float inner = fmaxf(p, part1[ch]);
        if (inner_len <= 0) inner = edge;  // no inner tokens -> start rep
        o[ch]       = edge * m;
        o[ch + 128] = inner * m;
    } else {
        o[ch + 256] = edge * m;
    }
}

extern "C" void kernel_launch(void* const* d_in, const int* in_sizes, int n_in,
                              void* d_out, int out_size)
{
    const float* token_reps = (const float*)d_in[0];
    const int2* span_ids    = (const int2*)d_in[1];
    const int* span_masks   = (const int*)d_in[2];
    float* out              = (float*)d_out;

    // 1 span per CTA, 8 warps each -> 1024 CTAs, 8192 warps.
    span_rep_kernel<<<SRL_NSPANS, 256>>>(token_reps, span_ids, span_masks, out);
}